// round 12
// baseline (speedup 1.0000x reference)
#include <cuda_runtime.h>
#include <cuda_bf16.h>
#include <cstdint>
#include <math.h>

// Problem shapes (fixed)
#define NX 4096
#define NY 16384
#define CX 128
#define CY 128
#define OD 256
#define KIN 256
#define BIGD 1e30f
#define W_EPS 1e-16f
#define LN_EPS 1e-5f

// Global scratch
__device__ __nv_bfloat16 g_Wh[OD * KIN];
__device__ __nv_bfloat16 g_Wl[OD * KIN];
__device__ float4 g_pos4[NX];                 // (x,y,z,|p|^2)

// ---------------------------------------------------------------------------
// Helpers (baseline PTX, valid for compute_100)
// ---------------------------------------------------------------------------
static __device__ __forceinline__ uint32_t smem_u32(const void* p) {
    uint32_t a;
    asm("{ .reg .u64 t; cvta.to.shared.u64 t, %1; cvt.u32.u64 %0, t; }"
        : "=r"(a) : "l"(p));
    return a;
}

static __device__ __forceinline__ void ldsm_x4(uint32_t addr, uint32_t* r) {
    asm volatile("ldmatrix.sync.aligned.m8n8.x4.shared.b16 {%0,%1,%2,%3}, [%4];"
                 : "=r"(r[0]), "=r"(r[1]), "=r"(r[2]), "=r"(r[3]) : "r"(addr));
}

static __device__ __forceinline__ void mma_bf16(float* d, const uint32_t* a,
                                                uint32_t b0, uint32_t b1) {
    asm volatile(
        "mma.sync.aligned.m16n8k16.row.col.f32.bf16.bf16.f32 "
        "{%0,%1,%2,%3},{%4,%5,%6,%7},{%8,%9},{%0,%1,%2,%3};"
        : "+f"(d[0]), "+f"(d[1]), "+f"(d[2]), "+f"(d[3])
        : "r"(a[0]), "r"(a[1]), "r"(a[2]), "r"(a[3]), "r"(b0), "r"(b1));
}

static __device__ __forceinline__ void cp_async16(uint32_t dst, const void* src) {
    asm volatile("cp.async.cg.shared.global [%0], [%1], 16;" :: "r"(dst), "l"(src));
}
static __device__ __forceinline__ void cp_commit() {
    asm volatile("cp.async.commit_group;" ::: "memory");
}
template <int N>
static __device__ __forceinline__ void cp_wait() {
    asm volatile("cp.async.wait_group %0;" :: "n"(N) : "memory");
}

#define BAR_ARRIVE(id, cnt) \
    asm volatile("bar.arrive %0, %1;" :: "r"(id), "r"(cnt) : "memory")
#define BAR_SYNC(id, cnt) \
    asm volatile("bar.sync %0, %1;" :: "r"(id), "r"(cnt) : "memory")

// Fast hi/lo bf16 split of a float pair
static __device__ __forceinline__ void split_pair(float v0, float v1,
                                                  uint32_t& hp, uint32_t& lp) {
    uint32_t u0 = __float_as_uint(v0), u1 = __float_as_uint(v1);
    asm("prmt.b32 %0, %1, %2, 0x7632;" : "=r"(hp) : "r"(u0), "r"(u1));
    float h0 = __uint_as_float(u0 & 0xFFFF0000u);
    float h1 = __uint_as_float(u1 & 0xFFFF0000u);
    float l0 = v0 - h0, l1 = v1 - h1;
    asm("cvt.rn.bf16x2.f32 %0, %1, %2;" : "=r"(lp) : "f"(l1), "f"(l0));
}

// Exact branchless top-3 insert (distance only; fp ties measure-zero)
static __device__ __forceinline__ void ins3(float d, int j,
                                            float& d0, float& d1, float& d2,
                                            int& i0, int& i1, int& i2) {
    bool lt0 = d < d0, lt1 = d < d1, lt2 = d < d2;
    d2 = lt1 ? d1 : (lt2 ? d : d2); i2 = lt1 ? i1 : (lt2 ? j : i2);
    d1 = lt0 ? d0 : (lt1 ? d : d1); i1 = lt0 ? i0 : (lt1 ? j : i1);
    d0 = lt0 ? d  : d0;             i0 = lt0 ? j  : i0;
}

// ---------------------------------------------------------------------------
// Kernel 0: W split + pos4 pack
// ---------------------------------------------------------------------------
__global__ __launch_bounds__(256)
void prep_small_kernel(const float* __restrict__ W,
                       const float* __restrict__ pos_x) {
    if (blockIdx.x < 32) {
        int base = blockIdx.x * (256 * 4) + threadIdx.x;
        uint32_t* wh = (uint32_t*)g_Wh;
        uint32_t* wl = (uint32_t*)g_Wl;
#pragma unroll
        for (int i = 0; i < 4; i++) {
            int p = base + i * 256;
            float2 v = *(const float2*)&W[p * 2];
            split_pair(v.x, v.y, wh[p], wl[p]);
        }
    } else {
        int idx = (int)(blockIdx.x - 32) * 256 + threadIdx.x;
        if (idx < NX) {
            float x = pos_x[idx * 3 + 0];
            float y = pos_x[idx * 3 + 1];
            float z = pos_x[idx * 3 + 2];
            g_pos4[idx] = make_float4(x, y, z, x * x + y * y + z * z);
        }
    }
}

// ---------------------------------------------------------------------------
// Kernel 1 (FUSED, warp-specialized):
//   warps 0-7  : KNN+interp producers -> A tile buffers (2 tiles of 64 rows)
//   warps 8-15 : MMA consumers (bf16 3-term hi/lo GEMM) + LN + ReLU
// SMEM (219648 B):
//   A0h@0  A0l@33792  A1h@67584  A1l@101376     (each 33792, stride 528)
//   B buf  @135168 (hi@+0, lo@+20480; 40960)    single buffer, stride 80
//   POS    @176128 (40960 = 2560 float4)
//   STATS  @217088 (2560)
// Named barriers: 0=preamble syncthreads, 1=MMA-group(256), 2=KNN-group(256),
//                 3=A0-ready(512), 4=A1-ready(512)
// ---------------------------------------------------------------------------
#define SROW 528
#define A0H 0
#define A0L 33792
#define A1H 67584
#define A1L 101376
#define ALDELTA 33792
#define BBASE 135168
#define BLOF 20480
#define BSTR 80
#define POS 176128
#define STATS 217088
#define G_TOTAL 219648
#define MAXPTS 2560

__global__ __launch_bounds__(512, 1)
void fused_kernel(const float* __restrict__ pos_x,
                  const float* __restrict__ xfeat,
                  const int*   __restrict__ batch_x,
                  const float* __restrict__ pos_y,
                  const float* __restrict__ yfeat,
                  const int*   __restrict__ batch_y,
                  const float* __restrict__ gamma,
                  const float* __restrict__ beta,
                  float* __restrict__ out)
{
    extern __shared__ char smem[];
    const uint32_t sb = smem_u32(smem);
    __shared__ int sbounds[9];

    const int tid  = threadIdx.x;
    const int wid  = tid >> 5;
    const int lane = tid & 31;
    const int rowBase = blockIdx.x * 128;

    if (tid < 9) {
        int t = tid;
        int lo = 0, hi = NX;
        while (lo < hi) { int m = (lo + hi) >> 1; if (batch_x[m] < t) lo = m + 1; else hi = m; }
        sbounds[t] = lo;
    }
    __syncthreads();     // barrier 0 — last CTA-wide sync before specialization

    // =======================================================================
    // KNN PRODUCER GROUP (warps 0-7)
    // =======================================================================
    if (wid < 8) {
        const int bmin = batch_y[rowBase];
        const int bmax = batch_y[rowBase + 127];
        const int s0   = sbounds[bmin];
        const int e1   = sbounds[bmax + 1];
        const int n    = e1 - s0;
        const bool inSmem = (n <= MAXPTS);

        if (inSmem) {
            for (int i = tid; i < n; i += 256)
                *(float4*)(smem + POS + (uint32_t)i * 16) = g_pos4[s0 + i];
        }
        BAR_SYNC(2, 256);            // KNN-group: pos cache ready

        for (int tile = 0; tile < 2; tile++) {
            const uint32_t AH = tile ? A1H : A0H;
#pragma unroll 1
            for (int q = 0; q < 8; q++) {
                const int yloc = wid * 8 + q;
                const int yi   = rowBase + tile * 64 + yloc;

                const float py0 = pos_y[yi * 3 + 0];
                const float py1 = pos_y[yi * 3 + 1];
                const float py2 = pos_y[yi * 3 + 2];
                const float ny2 = py0 * py0 + py1 * py1 + py2 * py2;
                const int b = batch_y[yi];
                const int s = sbounds[b];
                const int e = sbounds[b + 1];

                float dA0 = BIGD, dA1 = BIGD, dA2 = BIGD;
                int   iA0 = 0,    iA1 = 0,    iA2 = 0;
                float dB0 = BIGD, dB1 = BIGD, dB2 = BIGD;
                int   iB0 = 0,    iB1 = 0,    iB2 = 0;

                if (inSmem) {
                    const int ls = s - s0, le = e - s0;
                    int jl = ls + lane;
                    for (; jl + 32 < le; jl += 64) {
                        float4 pa = *(const float4*)(smem + POS + (uint32_t)jl * 16);
                        float4 pb = *(const float4*)(smem + POS + (uint32_t)(jl + 32) * 16);
                        float da = fmaxf(ny2 + pa.w - 2.0f * (py0 * pa.x + py1 * pa.y + py2 * pa.z), 0.0f);
                        float db = fmaxf(ny2 + pb.w - 2.0f * (py0 * pb.x + py1 * pb.y + py2 * pb.z), 0.0f);
                        ins3(da, s0 + jl,      dA0, dA1, dA2, iA0, iA1, iA2);
                        ins3(db, s0 + jl + 32, dB0, dB1, dB2, iB0, iB1, iB2);
                    }
                    if (jl < le) {
                        float4 pa = *(const float4*)(smem + POS + (uint32_t)jl * 16);
                        float da = fmaxf(ny2 + pa.w - 2.0f * (py0 * pa.x + py1 * pa.y + py2 * pa.z), 0.0f);
                        ins3(da, s0 + jl, dA0, dA1, dA2, iA0, iA1, iA2);
                    }
                } else {
                    for (int j = s + lane; j < e; j += 32) {
                        float4 pa = g_pos4[j];
                        float da = fmaxf(ny2 + pa.w - 2.0f * (py0 * pa.x + py1 * pa.y + py2 * pa.z), 0.0f);
                        ins3(da, j, dA0, dA1, dA2, iA0, iA1, iA2);
                    }
                }
                ins3(dB0, iB0, dA0, dA1, dA2, iA0, iA1, iA2);
                ins3(dB1, iB1, dA0, dA1, dA2, iA0, iA1, iA2);
                ins3(dB2, iB2, dA0, dA1, dA2, iA0, iA1, iA2);

                for (int off = 16; off; off >>= 1) {
                    float od0 = __shfl_xor_sync(0xffffffffu, dA0, off);
                    float od1 = __shfl_xor_sync(0xffffffffu, dA1, off);
                    float od2 = __shfl_xor_sync(0xffffffffu, dA2, off);
                    int   oi0 = __shfl_xor_sync(0xffffffffu, iA0, off);
                    int   oi1 = __shfl_xor_sync(0xffffffffu, iA1, off);
                    int   oi2 = __shfl_xor_sync(0xffffffffu, iA2, off);
                    ins3(od0, oi0, dA0, dA1, dA2, iA0, iA1, iA2);
                    ins3(od1, oi1, dA0, dA1, dA2, iA0, iA1, iA2);
                    ins3(od2, oi2, dA0, dA1, dA2, iA0, iA1, iA2);
                }

                const float w0 = 1.0f / fmaxf(dA0, W_EPS);
                const float w1 = 1.0f / fmaxf(dA1, W_EPS);
                const float w2 = 1.0f / fmaxf(dA2, W_EPS);
                const float inv_wsum = 1.0f / (w0 + w1 + w2);

                const float* f0 = xfeat + (size_t)iA0 * CX;
                const float* f1 = xfeat + (size_t)iA1 * CX;
                const float* f2 = xfeat + (size_t)iA2 * CX;
                const float* fy = yfeat + (size_t)yi * CY;

                const int c = lane * 4;
                float4 a0 = *(const float4*)&f0[c];
                float4 a1 = *(const float4*)&f1[c];
                float4 a2 = *(const float4*)&f2[c];
                float4 ay = *(const float4*)&fy[c];
                float v0 = (w0 * a0.x + w1 * a1.x + w2 * a2.x) * inv_wsum;
                float v1 = (w0 * a0.y + w1 * a1.y + w2 * a2.y) * inv_wsum;
                float v2 = (w0 * a0.z + w1 * a1.z + w2 * a2.z) * inv_wsum;
                float v3 = (w0 * a0.w + w1 * a1.w + w2 * a2.w) * inv_wsum;

                const uint32_t arow = (uint32_t)(yloc * SROW + lane * 8);
                uint2 hp, lp;
                split_pair(v0, v1, hp.x, lp.x);
                split_pair(v2, v3, hp.y, lp.y);
                *(uint2*)(smem + AH + arow) = hp;
                *(uint2*)(smem + AH + ALDELTA + arow) = lp;
                split_pair(ay.x, ay.y, hp.x, lp.x);
                split_pair(ay.z, ay.w, hp.y, lp.y);
                *(uint2*)(smem + AH + arow + 256) = hp;
                *(uint2*)(smem + AH + ALDELTA + arow + 256) = lp;
            }
            __threadfence_block();
            BAR_ARRIVE(3 + tile, 512);     // A tile ready
        }
        return;                            // producers exit
    }

    // =======================================================================
    // MMA CONSUMER GROUP (warps 8-15)
    // =======================================================================
    const int tid2 = tid - 256;
    const int wid2 = wid - 8;
    const int g    = lane >> 2;
    const int tig  = lane & 3;
    const int mw   = (wid2 >> 2) * 32;     // warp row base (0/32)
    const int nw   = wid2 & 3;             // warp col base = nw*64

    auto load_B = [&](int p) {
        const int kof = p * 32;
#pragma unroll
        for (int i = 0; i < 4; i++) {
            int idx = tid2 + i * 256;      // 0..1023
            int r = idx >> 2, kc = idx & 3;
            const size_t gs = (size_t)r * KIN + kof + kc * 8;
            uint32_t off = (uint32_t)(r * BSTR + kc * 16);
            cp_async16(sb + BBASE + off, &g_Wh[gs]);
            cp_async16(sb + BBASE + BLOF + off, &g_Wl[gs]);
        }
        cp_commit();
    };

    load_B(0);                             // prefetch during KNN tile 0

    const int quad  = lane >> 3;
    const int lrow  = lane & 7;
    const int aRow  = (quad & 1) * 8 + lrow;
    const int aKoff = (quad >> 1) * 8;
    const int bRow  = ((lane >> 4) * 8) + lrow;
    const int bKoff = ((lane >> 3) & 1) * 8;
    const uint32_t offB = (uint32_t)((nw * 64 + bRow) * BSTR + bKoff * 2);
    const uint32_t aCol = (uint32_t)((mw + aRow) * SROW + aKoff * 2);

    float* sSum = (float*)(smem + STATS);  // [64][4]
    float* sSq  = sSum + 256;
    float* sMu  = sSq + 256;
    float* sRs  = sMu + 64;

#pragma unroll 1
    for (int tile = 0; tile < 2; tile++) {
        BAR_SYNC(3 + tile, 512);           // wait A tile from producers
        const uint32_t AH = tile ? A1H : A0H;

        float acc[2][8][4];
#pragma unroll
        for (int mt = 0; mt < 2; mt++)
#pragma unroll
            for (int nt = 0; nt < 8; nt++)
#pragma unroll
                for (int j = 0; j < 4; j++) acc[mt][nt][j] = 0.f;

#pragma unroll 1
        for (int p = 0; p < 8; p++) {
            if (tile > 0 || p > 0) {
                BAR_SYNC(1, 256);          // prev B fully consumed
                load_B(p);
            }
            cp_wait<0>();
            BAR_SYNC(1, 256);              // B ready for all MMA warps

            const uint32_t bB = sb + BBASE + offB;
            const uint32_t aB = sb + AH + aCol + (uint32_t)(p * 64);

#pragma unroll
            for (int ks = 0; ks < 2; ks++) {
                const uint32_t kb = (uint32_t)(ks * 32);
                uint32_t Bh[16], Bl[16];
#pragma unroll
                for (int i = 0; i < 4; i++) {
                    uint32_t ba = bB + (uint32_t)(i * 16 * BSTR) + kb;
                    ldsm_x4(ba, &Bh[i * 4]);
                    ldsm_x4(ba + BLOF, &Bl[i * 4]);
                }
#pragma unroll
                for (int mt = 0; mt < 2; mt++) {
                    uint32_t Ah[4], Al[4];
                    const uint32_t aa = aB + (uint32_t)(mt * 16 * SROW) + kb;
                    ldsm_x4(aa, Ah);
                    ldsm_x4(aa + ALDELTA, Al);
#pragma unroll
                    for (int nt = 0; nt < 8; nt++)
                        mma_bf16(acc[mt][nt], Ah, Bh[2 * nt], Bh[2 * nt + 1]);
#pragma unroll
                    for (int nt = 0; nt < 8; nt++)
                        mma_bf16(acc[mt][nt], Al, Bh[2 * nt], Bh[2 * nt + 1]);
#pragma unroll
                    for (int nt = 0; nt < 8; nt++)
                        mma_bf16(acc[mt][nt], Ah, Bl[2 * nt], Bl[2 * nt + 1]);
                }
            }
        }
        BAR_SYNC(1, 256);                  // mainloop done; stats region safe

        // ---- LayerNorm stats ----
#pragma unroll
        for (int mt = 0; mt < 2; mt++)
#pragma unroll
            for (int half = 0; half < 2; half++) {
                float s = 0.f, q = 0.f;
#pragma unroll
                for (int nt = 0; nt < 8; nt++)
#pragma unroll
                    for (int j = 0; j < 2; j++) {
                        float v = acc[mt][nt][half * 2 + j];
                        s += v; q += v * v;
                    }
                s += __shfl_xor_sync(0xffffffffu, s, 1);
                q += __shfl_xor_sync(0xffffffffu, q, 1);
                s += __shfl_xor_sync(0xffffffffu, s, 2);
                q += __shfl_xor_sync(0xffffffffu, q, 2);
                if (tig == 0) {
                    int row = mw + mt * 16 + half * 8 + g;
                    sSum[row * 4 + nw] = s;
                    sSq[row * 4 + nw]  = q;
                }
            }
        BAR_SYNC(1, 256);

        if (tid2 < 64) {
            float s = sSum[tid2 * 4] + sSum[tid2 * 4 + 1] + sSum[tid2 * 4 + 2] + sSum[tid2 * 4 + 3];
            float q = sSq[tid2 * 4] + sSq[tid2 * 4 + 1] + sSq[tid2 * 4 + 2] + sSq[tid2 * 4 + 3];
            float mu = s * (1.0f / OD);
            float var = fmaxf(q * (1.0f / OD) - mu * mu, 0.0f);
            sMu[tid2] = mu;
            sRs[tid2] = rsqrtf(var + LN_EPS);
        }
        BAR_SYNC(1, 256);

        // ---- normalize + affine + ReLU + store ----
#pragma unroll
        for (int mt = 0; mt < 2; mt++)
#pragma unroll
            for (int half = 0; half < 2; half++) {
                int row = mw + mt * 16 + half * 8 + g;
                float mu = sMu[row];
                float rs = sRs[row];
                float* orow = out + (size_t)(rowBase + tile * 64 + row) * OD;
#pragma unroll
                for (int nt = 0; nt < 8; nt++) {
                    int col = nw * 64 + nt * 8 + tig * 2;
                    float2 gb0 = *(const float2*)&gamma[col];
                    float2 bb0 = *(const float2*)&beta[col];
                    float v0 = acc[mt][nt][half * 2 + 0];
                    float v1 = acc[mt][nt][half * 2 + 1];
                    float2 r2;
                    r2.x = fmaxf((v0 - mu) * rs * gb0.x + bb0.x, 0.0f);
                    r2.y = fmaxf((v1 - mu) * rs * gb0.y + bb0.y, 0.0f);
                    *(float2*)&orow[col] = r2;
                }
            }
        BAR_SYNC(1, 256);                  // stats region reusable next tile
    }
}

// ---------------------------------------------------------------------------
extern "C" void kernel_launch(void* const* d_in, const int* in_sizes, int n_in,
                              void* d_out, int out_size)
{
    const float* pos_x   = (const float*)d_in[0];
    const float* xfeat   = (const float*)d_in[1];
    const int*   batch_x = (const int*)  d_in[2];
    const float* pos_y   = (const float*)d_in[3];
    const float* yfeat   = (const float*)d_in[4];
    const int*   batch_y = (const int*)  d_in[5];
    const float* W       = (const float*)d_in[6];
    const float* gamma   = (const float*)d_in[7];
    const float* beta    = (const float*)d_in[8];
    float* out = (float*)d_out;

    prep_small_kernel<<<48, 256>>>(W, pos_x);

    cudaFuncSetAttribute(fused_kernel,
                         cudaFuncAttributeMaxDynamicSharedMemorySize, G_TOTAL);
    fused_kernel<<<NY / 128, 512, G_TOTAL>>>(pos_x, xfeat, batch_x, pos_y,
                                             yfeat, batch_y, gamma, beta, out);
}

// round 13
// speedup vs baseline: 1.1574x; 1.1574x over previous
#include <cuda_runtime.h>
#include <cuda_bf16.h>
#include <cstdint>
#include <math.h>

// Problem shapes (fixed)
#define NX 4096
#define NY 16384
#define CX 128
#define CY 128
#define OD 256
#define KIN 256
#define BIGD 1e30f
#define W_EPS 1e-16f
#define LN_EPS 1e-5f

// Global scratch
__device__ __nv_bfloat16 g_Wh[OD * KIN];
__device__ __nv_bfloat16 g_Wl[OD * KIN];
__device__ float4 g_pos4[NX];                 // (x,y,z,|p|^2)

// ---------------------------------------------------------------------------
// Helpers (baseline PTX, valid for compute_100)
// ---------------------------------------------------------------------------
static __device__ __forceinline__ uint32_t smem_u32(const void* p) {
    uint32_t a;
    asm("{ .reg .u64 t; cvta.to.shared.u64 t, %1; cvt.u32.u64 %0, t; }"
        : "=r"(a) : "l"(p));
    return a;
}

static __device__ __forceinline__ void ldsm_x4(uint32_t addr, uint32_t* r) {
    asm volatile("ldmatrix.sync.aligned.m8n8.x4.shared.b16 {%0,%1,%2,%3}, [%4];"
                 : "=r"(r[0]), "=r"(r[1]), "=r"(r[2]), "=r"(r[3]) : "r"(addr));
}

static __device__ __forceinline__ void mma_bf16(float* d, const uint32_t* a,
                                                uint32_t b0, uint32_t b1) {
    asm volatile(
        "mma.sync.aligned.m16n8k16.row.col.f32.bf16.bf16.f32 "
        "{%0,%1,%2,%3},{%4,%5,%6,%7},{%8,%9},{%0,%1,%2,%3};"
        : "+f"(d[0]), "+f"(d[1]), "+f"(d[2]), "+f"(d[3])
        : "r"(a[0]), "r"(a[1]), "r"(a[2]), "r"(a[3]), "r"(b0), "r"(b1));
}

static __device__ __forceinline__ void cp_async16(uint32_t dst, const void* src) {
    asm volatile("cp.async.cg.shared.global [%0], [%1], 16;" :: "r"(dst), "l"(src));
}
static __device__ __forceinline__ void cp_commit() {
    asm volatile("cp.async.commit_group;" ::: "memory");
}
template <int N>
static __device__ __forceinline__ void cp_wait() {
    asm volatile("cp.async.wait_group %0;" :: "n"(N) : "memory");
}

// Fast hi/lo bf16 split of a float pair
static __device__ __forceinline__ void split_pair(float v0, float v1,
                                                  uint32_t& hp, uint32_t& lp) {
    uint32_t u0 = __float_as_uint(v0), u1 = __float_as_uint(v1);
    asm("prmt.b32 %0, %1, %2, 0x7632;" : "=r"(hp) : "r"(u0), "r"(u1));
    float h0 = __uint_as_float(u0 & 0xFFFF0000u);
    float h1 = __uint_as_float(u1 & 0xFFFF0000u);
    float l0 = v0 - h0, l1 = v1 - h1;
    asm("cvt.rn.bf16x2.f32 %0, %1, %2;" : "=r"(lp) : "f"(l1), "f"(l0));
}

// Exact branchless top-3 insert
static __device__ __forceinline__ void ins3(float d, int j,
                                            float& d0, float& d1, float& d2,
                                            int& i0, int& i1, int& i2) {
    bool lt0 = d < d0, lt1 = d < d1, lt2 = d < d2;
    d2 = lt1 ? d1 : (lt2 ? d : d2); i2 = lt1 ? i1 : (lt2 ? j : i2);
    d1 = lt0 ? d0 : (lt1 ? d : d1); i1 = lt0 ? i0 : (lt1 ? j : i1);
    d0 = lt0 ? d  : d0;             i0 = lt0 ? j  : i0;
}

// ---------------------------------------------------------------------------
// Kernel 0: W split + pos4 pack
// ---------------------------------------------------------------------------
__global__ __launch_bounds__(256)
void prep_small_kernel(const float* __restrict__ W,
                       const float* __restrict__ pos_x) {
    if (blockIdx.x < 32) {
        int base = blockIdx.x * (256 * 4) + threadIdx.x;
        uint32_t* wh = (uint32_t*)g_Wh;
        uint32_t* wl = (uint32_t*)g_Wl;
#pragma unroll
        for (int i = 0; i < 4; i++) {
            int p = base + i * 256;
            float2 v = *(const float2*)&W[p * 2];
            split_pair(v.x, v.y, wh[p], wl[p]);
        }
    } else {
        int idx = (int)(blockIdx.x - 32) * 256 + threadIdx.x;
        if (idx < NX) {
            float x = pos_x[idx * 3 + 0];
            float y = pos_x[idx * 3 + 1];
            float z = pos_x[idx * 3 + 2];
            g_pos4[idx] = make_float4(x, y, z, x * x + y * y + z * z);
        }
    }
}

// ---------------------------------------------------------------------------
// Kernel 1 (FUSED, R9 structure): KNN(2q x 2cand ILP) -> A tile -> 3-term
// bf16 hi/lo GEMM -> LN + ReLU.  128 CTAs x 512 thr, 16 warps (2m x 8n).
// SMEM (217088 B): A_hi@0 (67584), A_lo@67584, POS/B@135168 (81920)
// ---------------------------------------------------------------------------
#define SROW 528
#define A_HI 0
#define A_LO 67584
#define POSB 135168
#define BSTR 80
#define BBUF 40960
#define BLOF 20480
#define G_TOTAL 217088

__global__ __launch_bounds__(512, 1)
void fused_kernel(const float* __restrict__ pos_x,
                  const float* __restrict__ xfeat,
                  const int*   __restrict__ batch_x,
                  const float* __restrict__ pos_y,
                  const float* __restrict__ yfeat,
                  const int*   __restrict__ batch_y,
                  const float* __restrict__ gamma,
                  const float* __restrict__ beta,
                  float* __restrict__ out)
{
    extern __shared__ char smem[];
    const uint32_t sb = smem_u32(smem);
    __shared__ int sbounds[9];

    const int tid  = threadIdx.x;
    const int wid  = tid >> 5;
    const int lane = tid & 31;
    const int rowBase = blockIdx.x * 128;

    if (tid < 9) {
        int t = tid;
        int lo = 0, hi = NX;
        while (lo < hi) { int m = (lo + hi) >> 1; if (batch_x[m] < t) lo = m + 1; else hi = m; }
        sbounds[t] = lo;
    }
    __syncthreads();

    const int bmin = batch_y[rowBase];
    const int bmax = batch_y[rowBase + 127];
    const int s0   = sbounds[bmin];
    const int e1   = sbounds[bmax + 1];
    const int n    = e1 - s0;
    const bool early  = (n <= 2560);
    const bool inSmem = (n <= 5120);
    const uint32_t posOff = POSB + (early ? BBUF : 0);

    // ---- B phase loader ----
    auto load_B = [&](int p, uint32_t bb) {
        const int kof = p * 32;
#pragma unroll
        for (int i = 0; i < 2; i++) {
            int idx = tid + i * 512;
            int r = idx >> 2, kc = idx & 3;
            const size_t gs = (size_t)r * KIN + kof + kc * 8;
            uint32_t off = (uint32_t)(r * BSTR + kc * 16);
            cp_async16(bb + off, &g_Wh[gs]);
            cp_async16(bb + BLOF + off, &g_Wl[gs]);
        }
        cp_commit();
    };

    if (early) load_B(0, sb + POSB);

    // ---- stage pos4 segment ----
    if (inSmem) {
        for (int i = tid; i < n; i += 512)
            *(float4*)(smem + posOff + (uint32_t)i * 16) = g_pos4[s0 + i];
    }
    __syncthreads();

    // ---- interp writer (shared by both queries) ----
    auto write_row = [&](int yi, int yloc, float d0, float d1, float d2,
                         int i0, int i1, int i2) {
        const float w0 = 1.0f / fmaxf(d0, W_EPS);
        const float w1 = 1.0f / fmaxf(d1, W_EPS);
        const float w2 = 1.0f / fmaxf(d2, W_EPS);
        const float inv_wsum = 1.0f / (w0 + w1 + w2);
        const float* f0 = xfeat + (size_t)i0 * CX;
        const float* f1 = xfeat + (size_t)i1 * CX;
        const float* f2 = xfeat + (size_t)i2 * CX;
        const float* fy = yfeat + (size_t)yi * CY;
        const int c = lane * 4;
        float4 a0 = *(const float4*)&f0[c];
        float4 a1 = *(const float4*)&f1[c];
        float4 a2 = *(const float4*)&f2[c];
        float4 ay = *(const float4*)&fy[c];
        float v0 = (w0 * a0.x + w1 * a1.x + w2 * a2.x) * inv_wsum;
        float v1 = (w0 * a0.y + w1 * a1.y + w2 * a2.y) * inv_wsum;
        float v2 = (w0 * a0.z + w1 * a1.z + w2 * a2.z) * inv_wsum;
        float v3 = (w0 * a0.w + w1 * a1.w + w2 * a2.w) * inv_wsum;
        const uint32_t arow = (uint32_t)(yloc * SROW + lane * 8);
        uint2 hp, lp;
        split_pair(v0, v1, hp.x, lp.x);
        split_pair(v2, v3, hp.y, lp.y);
        *(uint2*)(smem + A_HI + arow) = hp;
        *(uint2*)(smem + A_LO + arow) = lp;
        split_pair(ay.x, ay.y, hp.x, lp.x);
        split_pair(ay.z, ay.w, hp.y, lp.y);
        *(uint2*)(smem + A_HI + arow + 256) = hp;
        *(uint2*)(smem + A_LO + arow + 256) = lp;
    };

    // warp merge for one query's top-3
    auto warp_merge = [&](float& d0, float& d1, float& d2,
                          int& i0, int& i1, int& i2) {
        for (int off = 16; off; off >>= 1) {
            float od0 = __shfl_xor_sync(0xffffffffu, d0, off);
            float od1 = __shfl_xor_sync(0xffffffffu, d1, off);
            float od2 = __shfl_xor_sync(0xffffffffu, d2, off);
            int   oi0 = __shfl_xor_sync(0xffffffffu, i0, off);
            int   oi1 = __shfl_xor_sync(0xffffffffu, i1, off);
            int   oi2 = __shfl_xor_sync(0xffffffffu, i2, off);
            ins3(od0, oi0, d0, d1, d2, i0, i1, i2);
            ins3(od1, oi1, d0, d1, d2, i0, i1, i2);
            ins3(od2, oi2, d0, d1, d2, i0, i1, i2);
        }
    };

    // ---- KNN: each warp handles 8 rows as 4 query-pairs ----
#pragma unroll 1
    for (int t = 0; t < 4; t++) {
        const int ylocA = wid * 8 + 2 * t;
        const int ylocB = ylocA + 1;
        const int yiA = rowBase + ylocA;
        const int yiB = rowBase + ylocB;

        const float ax = pos_y[yiA * 3 + 0];
        const float ay_ = pos_y[yiA * 3 + 1];
        const float az = pos_y[yiA * 3 + 2];
        const float na2 = ax * ax + ay_ * ay_ + az * az;
        const float bx = pos_y[yiB * 3 + 0];
        const float by = pos_y[yiB * 3 + 1];
        const float bz = pos_y[yiB * 3 + 2];
        const float nb2 = bx * bx + by * by + bz * bz;

        const int ba = batch_y[yiA];
        const int bb_ = batch_y[yiB];
        const int sa = sbounds[ba], ea = sbounds[ba + 1];
        const int sb2 = sbounds[bb_], eb = sbounds[bb_ + 1];

        // chains: P,Q for query A; R,S for query B
        float dP0 = BIGD, dP1 = BIGD, dP2 = BIGD; int iP0 = 0, iP1 = 0, iP2 = 0;
        float dQ0 = BIGD, dQ1 = BIGD, dQ2 = BIGD; int iQ0 = 0, iQ1 = 0, iQ2 = 0;
        float dR0 = BIGD, dR1 = BIGD, dR2 = BIGD; int iR0 = 0, iR1 = 0, iR2 = 0;
        float dS0 = BIGD, dS1 = BIGD, dS2 = BIGD; int iS0 = 0, iS1 = 0, iS2 = 0;

        if (inSmem && sa == sb2 && ea == eb) {
            // FAST: dual-query dual-candidate
            const int ls = sa - s0, le = ea - s0;
            int jl = ls + lane;
            for (; jl + 32 < le; jl += 64) {
                float4 p0 = *(const float4*)(smem + posOff + (uint32_t)jl * 16);
                float4 p1 = *(const float4*)(smem + posOff + (uint32_t)(jl + 32) * 16);
                float dA0 = fmaxf(na2 + p0.w - 2.0f * (ax * p0.x + ay_ * p0.y + az * p0.z), 0.0f);
                float dA1 = fmaxf(na2 + p1.w - 2.0f * (ax * p1.x + ay_ * p1.y + az * p1.z), 0.0f);
                float dB0 = fmaxf(nb2 + p0.w - 2.0f * (bx * p0.x + by * p0.y + bz * p0.z), 0.0f);
                float dB1 = fmaxf(nb2 + p1.w - 2.0f * (bx * p1.x + by * p1.y + bz * p1.z), 0.0f);
                ins3(dA0, s0 + jl,      dP0, dP1, dP2, iP0, iP1, iP2);
                ins3(dA1, s0 + jl + 32, dQ0, dQ1, dQ2, iQ0, iQ1, iQ2);
                ins3(dB0, s0 + jl,      dR0, dR1, dR2, iR0, iR1, iR2);
                ins3(dB1, s0 + jl + 32, dS0, dS1, dS2, iS0, iS1, iS2);
            }
            if (jl < le) {
                float4 p0 = *(const float4*)(smem + posOff + (uint32_t)jl * 16);
                float dA0 = fmaxf(na2 + p0.w - 2.0f * (ax * p0.x + ay_ * p0.y + az * p0.z), 0.0f);
                float dB0 = fmaxf(nb2 + p0.w - 2.0f * (bx * p0.x + by * p0.y + bz * p0.z), 0.0f);
                ins3(dA0, s0 + jl, dP0, dP1, dP2, iP0, iP1, iP2);
                ins3(dB0, s0 + jl, dR0, dR1, dR2, iR0, iR1, iR2);
            }
        } else if (inSmem) {
            for (int j = sa + lane; j < ea; j += 32) {
                float4 p = *(const float4*)(smem + posOff + (uint32_t)(j - s0) * 16);
                float d = fmaxf(na2 + p.w - 2.0f * (ax * p.x + ay_ * p.y + az * p.z), 0.0f);
                ins3(d, j, dP0, dP1, dP2, iP0, iP1, iP2);
            }
            for (int j = sb2 + lane; j < eb; j += 32) {
                float4 p = *(const float4*)(smem + posOff + (uint32_t)(j - s0) * 16);
                float d = fmaxf(nb2 + p.w - 2.0f * (bx * p.x + by * p.y + bz * p.z), 0.0f);
                ins3(d, j, dR0, dR1, dR2, iR0, iR1, iR2);
            }
        } else {
            for (int j = sa + lane; j < ea; j += 32) {
                float4 p = g_pos4[j];
                float d = fmaxf(na2 + p.w - 2.0f * (ax * p.x + ay_ * p.y + az * p.z), 0.0f);
                ins3(d, j, dP0, dP1, dP2, iP0, iP1, iP2);
            }
            for (int j = sb2 + lane; j < eb; j += 32) {
                float4 p = g_pos4[j];
                float d = fmaxf(nb2 + p.w - 2.0f * (bx * p.x + by * p.y + bz * p.z), 0.0f);
                ins3(d, j, dR0, dR1, dR2, iR0, iR1, iR2);
            }
        }

        // combine secondary chains into primary
        ins3(dQ0, iQ0, dP0, dP1, dP2, iP0, iP1, iP2);
        ins3(dQ1, iQ1, dP0, dP1, dP2, iP0, iP1, iP2);
        ins3(dQ2, iQ2, dP0, dP1, dP2, iP0, iP1, iP2);
        ins3(dS0, iS0, dR0, dR1, dR2, iR0, iR1, iR2);
        ins3(dS1, iS1, dR0, dR1, dR2, iR0, iR1, iR2);
        ins3(dS2, iS2, dR0, dR1, dR2, iR0, iR1, iR2);

        warp_merge(dP0, dP1, dP2, iP0, iP1, iP2);
        warp_merge(dR0, dR1, dR2, iR0, iR1, iR2);

        write_row(yiA, ylocA, dP0, dP1, dP2, iP0, iP1, iP2);
        write_row(yiB, ylocB, dR0, dR1, dR2, iR0, iR1, iR2);
    }
    __syncthreads();

    if (!early) load_B(0, sb + POSB);

    // ---- GEMM mainloop: 8 phases of K=32 ----
    const int g   = lane >> 2;
    const int tig = lane & 3;
    const int mw  = (wid >> 3) * 64;
    const int nw  = wid & 7;

    const int quad  = lane >> 3;
    const int lrow  = lane & 7;
    const int aRow  = (quad & 1) * 8 + lrow;
    const int aKoff = (quad >> 1) * 8;
    const int bRow  = ((lane >> 4) * 8) + lrow;
    const int bKoff = ((lane >> 3) & 1) * 8;
    const uint32_t offB = (uint32_t)((nw * 32 + bRow) * BSTR + bKoff * 2);
    const uint32_t aCol = (uint32_t)((mw + aRow) * SROW + aKoff * 2);

    float acc[4][4][4];
#pragma unroll
    for (int mt = 0; mt < 4; mt++)
#pragma unroll
        for (int nt = 0; nt < 4; nt++)
#pragma unroll
            for (int j = 0; j < 4; j++) acc[mt][nt][j] = 0.f;

#pragma unroll 1
    for (int p = 0; p < 8; p++) {
        if (p < 7) {
            load_B(p + 1, sb + POSB + (uint32_t)((p + 1) & 1) * BBUF);
            cp_wait<1>();
        } else {
            cp_wait<0>();
        }
        __syncthreads();

        const uint32_t bB = sb + POSB + (uint32_t)(p & 1) * BBUF + offB;
        const uint32_t aB = sb + A_HI + aCol + (uint32_t)(p * 64);

#pragma unroll
        for (int ks = 0; ks < 2; ks++) {
            const uint32_t kb = (uint32_t)(ks * 32);
            uint32_t Bh[8], Bl[8];
            ldsm_x4(bB + kb, Bh);
            ldsm_x4(bB + 1280 + kb, Bh + 4);
            ldsm_x4(bB + BLOF + kb, Bl);
            ldsm_x4(bB + BLOF + 1280 + kb, Bl + 4);
#pragma unroll
            for (int mt = 0; mt < 4; mt++) {
                uint32_t Ah[4], Al[4];
                const uint32_t aa = aB + (uint32_t)(mt * 16 * SROW) + kb;
                ldsm_x4(aa, Ah);
                ldsm_x4(aa + A_LO, Al);
#pragma unroll
                for (int nt = 0; nt < 4; nt++)
                    mma_bf16(acc[mt][nt], Ah, Bh[2 * nt], Bh[2 * nt + 1]);
#pragma unroll
                for (int nt = 0; nt < 4; nt++)
                    mma_bf16(acc[mt][nt], Al, Bh[2 * nt], Bh[2 * nt + 1]);
#pragma unroll
                for (int nt = 0; nt < 4; nt++)
                    mma_bf16(acc[mt][nt], Ah, Bl[2 * nt], Bl[2 * nt + 1]);
            }
        }
        __syncthreads();
    }

    // ---- LayerNorm stats (overlay B region) ----
    float* sSum = (float*)(smem + POSB);
    float* sSq  = sSum + 1024;
    float* sMu  = sSq + 1024;
    float* sRs  = sMu + 128;

#pragma unroll
    for (int mt = 0; mt < 4; mt++)
#pragma unroll
        for (int half = 0; half < 2; half++) {
            float s = 0.f, q = 0.f;
#pragma unroll
            for (int nt = 0; nt < 4; nt++)
#pragma unroll
                for (int j = 0; j < 2; j++) {
                    float v = acc[mt][nt][half * 2 + j];
                    s += v; q += v * v;
                }
            s += __shfl_xor_sync(0xffffffffu, s, 1);
            q += __shfl_xor_sync(0xffffffffu, q, 1);
            s += __shfl_xor_sync(0xffffffffu, s, 2);
            q += __shfl_xor_sync(0xffffffffu, q, 2);
            if (tig == 0) {
                int row = mw + mt * 16 + half * 8 + g;
                sSum[row * 8 + nw] = s;
                sSq[row * 8 + nw]  = q;
            }
        }
    __syncthreads();

    if (tid < 128) {
        float s = 0.f, q = 0.f;
#pragma unroll
        for (int i = 0; i < 8; i++) { s += sSum[tid * 8 + i]; q += sSq[tid * 8 + i]; }
        float mu = s * (1.0f / OD);
        float var = fmaxf(q * (1.0f / OD) - mu * mu, 0.0f);
        sMu[tid] = mu;
        sRs[tid] = rsqrtf(var + LN_EPS);
    }
    __syncthreads();

    // ---- normalize + affine + ReLU + store ----
#pragma unroll
    for (int mt = 0; mt < 4; mt++)
#pragma unroll
        for (int half = 0; half < 2; half++) {
            int row = mw + mt * 16 + half * 8 + g;
            float mu = sMu[row];
            float rs = sRs[row];
            float* orow = out + (size_t)(rowBase + row) * OD;
#pragma unroll
            for (int nt = 0; nt < 4; nt++) {
                int col = nw * 32 + nt * 8 + tig * 2;
                float2 gb0 = *(const float2*)&gamma[col];
                float2 bb0 = *(const float2*)&beta[col];
                float v0 = acc[mt][nt][half * 2 + 0];
                float v1 = acc[mt][nt][half * 2 + 1];
                float2 r2;
                r2.x = fmaxf((v0 - mu) * rs * gb0.x + bb0.x, 0.0f);
                r2.y = fmaxf((v1 - mu) * rs * gb0.y + bb0.y, 0.0f);
                *(float2*)&orow[col] = r2;
            }
        }
}

// ---------------------------------------------------------------------------
extern "C" void kernel_launch(void* const* d_in, const int* in_sizes, int n_in,
                              void* d_out, int out_size)
{
    const float* pos_x   = (const float*)d_in[0];
    const float* xfeat   = (const float*)d_in[1];
    const int*   batch_x = (const int*)  d_in[2];
    const float* pos_y   = (const float*)d_in[3];
    const float* yfeat   = (const float*)d_in[4];
    const int*   batch_y = (const int*)  d_in[5];
    const float* W       = (const float*)d_in[6];
    const float* gamma   = (const float*)d_in[7];
    const float* beta    = (const float*)d_in[8];
    float* out = (float*)d_out;

    prep_small_kernel<<<48, 256>>>(W, pos_x);

    cudaFuncSetAttribute(fused_kernel,
                         cudaFuncAttributeMaxDynamicSharedMemorySize, G_TOTAL);
    fused_kernel<<<NY / 128, 512, G_TOTAL>>>(pos_x, xfeat, batch_x, pos_y,
                                             yfeat, batch_y, gamma, beta, out);
}